// round 16
// baseline (speedup 1.0000x reference)
#include <cuda_runtime.h>
#include <cuda_bf16.h>
#include <stdint.h>

// Problem constants
#define B_   4
#define N_   2048
#define NF_  512
#define H_   8
#define D_   64
#define W_   4
#define NW_  512          // N_/W_
#define KEEP_ 64
#define QKVN 1536         // 3*H*D
#define NROWS (B_*H_*NW_) // 16384
#define BHND (B_*H_*N_*D_)

// GEMM tiling: 64x64x16, 128 threads
#define BK 16
#define TBN 64

// hetero interleave: 19456 = 19*1024 blocks; bid%19<3 -> qkv (3072), else topk (16384)
#define HET_BLOCKS 19456

typedef unsigned long long u64;

// ---------------- device scratch ----------------
__device__ float g_q[BHND];
__device__ float g_k[BHND];
__device__ float g_v[BHND];
__device__ float g_tab[(2*N_-1)*H_];      // 4095 x 8
__device__ int   g_idx[NROWS*KEEP_];
__device__ float g_attn[B_*N_*H_*D_];     // (B, N, H*D)

// ---------------- packed fp32x2 helpers ----------------
__device__ __forceinline__ u64 pack2(float v){
    u64 r; asm("mov.b64 %0, {%1, %1};" : "=l"(r) : "f"(v)); return r;
}
__device__ __forceinline__ void fma2(u64& c, u64 a, u64 b){
    asm("fma.rn.f32x2 %0, %1, %2, %0;" : "+l"(c) : "l"(a), "l"(b));
}
__device__ __forceinline__ float2 unpack2(u64 v){
    float lo, hi; asm("mov.b64 {%0, %1}, %2;" : "=f"(lo), "=f"(hi) : "l"(v));
    return make_float2(lo, hi);
}

// ---------------- cp.async helpers ----------------
__device__ __forceinline__ void cp_async16(uint32_t smem, const void* g){
    asm volatile("cp.async.ca.shared.global [%0], [%1], 16;" :: "r"(smem), "l"(g));
}
#define CP_COMMIT() asm volatile("cp.async.commit_group;" ::: "memory")
#define CP_WAIT0()  asm volatile("cp.async.wait_group 0;" ::: "memory")

// ---------------- threefry2x32 (JAX-compatible, key=(0,1)) ----------------
__device__ __forceinline__ uint32_t rotl32(uint32_t x, int r){ return (x<<r) | (x>>(32-r)); }

__device__ __forceinline__ void threefry_0_1(uint32_t c0, uint32_t c1, uint32_t& o0, uint32_t& o1){
    const uint32_t ks0 = 0u, ks1 = 1u, ks2 = 0x1BD11BDBu;
    uint32_t x0 = c0 + ks0;
    uint32_t x1 = c1 + ks1;
#define QR(r) { x0 += x1; x1 = rotl32(x1, r); x1 ^= x0; }
    QR(13) QR(15) QR(26) QR(6)   x0 += ks1; x1 += ks2 + 1u;
    QR(17) QR(29) QR(16) QR(24)  x0 += ks2; x1 += ks0 + 2u;
    QR(13) QR(15) QR(26) QR(6)   x0 += ks0; x1 += ks1 + 3u;
    QR(17) QR(29) QR(16) QR(24)  x0 += ks1; x1 += ks2 + 4u;
    QR(13) QR(15) QR(26) QR(6)   x0 += ks2; x1 += ks0 + 5u;
#undef QR
    o0 = x0; o1 = x1;
}

// ---------------- 128-thread block exclusive scan (4 warps) ----------------
__device__ __forceinline__ int scan128_excl(int val, int tid, int* scratch){
    int lane = tid & 31, wid = tid >> 5;
    int x = val;
#pragma unroll
    for (int o=1; o<32; o<<=1){
        int t = __shfl_up_sync(0xffffffffu, x, o);
        if (lane >= o) x += t;
    }
    if (lane == 31) scratch[wid] = x;
    __syncthreads();
    if (tid < 4){
        int y = scratch[tid];
#pragma unroll
        for (int o=1; o<4; o<<=1){
            int t = __shfl_up_sync(0xFu, y, o);
            if (tid >= o) y += t;
        }
        scratch[tid] = y;
    }
    __syncthreads();
    int base = (wid == 0) ? 0 : scratch[wid-1];
    return base + x - val;
}

// ---------------- hetero kernel: qkv GEMM role (3072) interleaved with topk role (16384) ----------------
__global__ __launch_bounds__(128) void hetero128_kernel(const float* __restrict__ A,
                                                        const float* __restrict__ Bm,
                                                        const float* __restrict__ bias)
{
    __shared__ float sbuf[4096];   // gemm: As[0..2048) Bs[2048..4096); topk: hist/scratch ints
    __shared__ unsigned s_prefix;
    __shared__ int s_target;

    const int bid = blockIdx.x;
    const int tid = threadIdx.x;
    const int grp = bid / 19, rem = bid - grp*19;

    if (rem < 3){
        // ================= QKV GEMM role (body = R15 qkv64_kernel, passed) =================
        const int sub = grp*3 + rem;              // 0..3071
        const int row0 = (sub / 24) * 64;         // 128 row tiles
        const int col0 = (sub % 24) * 64;         // 24 col tiles

        float* Asb = sbuf;          // [2][16][64]
        float* Bsb = sbuf + 2048;   // [2][16][64]

        const int ar = tid>>1;
        const int ac = (tid&1)*8;
        const int br = tid>>3;
        const int bc = (tid&7)*8;

        const int warp = tid>>5, lane = tid&31;
        const int wm = warp&1, wn = warp>>1;
        const int tr = lane>>3, tc = lane&7;
        const int m0 = wm*32 + tr*8;
        const int n0 = wn*32 + tc*4;

        const uint32_t bs_base = (uint32_t)__cvta_generic_to_shared(Bsb);
        const uint32_t boff0 = (uint32_t)(br*TBN + bc)*4u;
        const uint32_t boff1 = boff0 + 16u;

        u64 acc2[4][4];
#pragma unroll
        for (int i2=0;i2<4;i2++)
#pragma unroll
            for (int j=0;j<4;j++) acc2[i2][j]=0ull;

        cp_async16(bs_base + boff0, &Bm[br*QKVN + col0+bc]);
        cp_async16(bs_base + boff1, &Bm[br*QKVN + col0+bc+4]);
        CP_COMMIT();
        float4 pa0 = *(const float4*)&A[(long long)(row0+ar)*NF_ + ac];
        float4 pa1 = *(const float4*)&A[(long long)(row0+ar)*NF_ + ac+4];
        Asb[(ac+0)*64+ar] = pa0.x; Asb[(ac+1)*64+ar] = pa0.y; Asb[(ac+2)*64+ar] = pa0.z; Asb[(ac+3)*64+ar] = pa0.w;
        Asb[(ac+4)*64+ar] = pa1.x; Asb[(ac+5)*64+ar] = pa1.y; Asb[(ac+6)*64+ar] = pa1.z; Asb[(ac+7)*64+ar] = pa1.w;
        CP_WAIT0();
        __syncthreads();

        int buf = 0;
        const int NT = NF_/BK;
        for (int t=0; t<NT; t++){
            const int k0n = (t+1)*BK;
            const int nb = buf^1;
            if (t+1 < NT){
                uint32_t nbb = bs_base + (uint32_t)nb*(BK*TBN*4u);
                cp_async16(nbb + boff0, &Bm[(k0n+br)*QKVN + col0+bc]);
                cp_async16(nbb + boff1, &Bm[(k0n+br)*QKVN + col0+bc+4]);
                CP_COMMIT();
                pa0 = *(const float4*)&A[(long long)(row0+ar)*NF_ + k0n+ac];
                pa1 = *(const float4*)&A[(long long)(row0+ar)*NF_ + k0n+ac+4];
            }
#pragma unroll
            for (int kk=0; kk<BK; kk++){
                const u64* av = (const u64*)&Asb[buf*1024 + kk*64 + m0];
                u64 a0 = av[0], a1 = av[1], a2 = av[2], a3 = av[3];
                float4 b = *(const float4*)&Bsb[buf*1024 + kk*64 + n0];
                u64 bb0 = pack2(b.x), bb1 = pack2(b.y), bb2 = pack2(b.z), bb3 = pack2(b.w);
                fma2(acc2[0][0], a0, bb0); fma2(acc2[1][0], a1, bb0);
                fma2(acc2[2][0], a2, bb0); fma2(acc2[3][0], a3, bb0);
                fma2(acc2[0][1], a0, bb1); fma2(acc2[1][1], a1, bb1);
                fma2(acc2[2][1], a2, bb1); fma2(acc2[3][1], a3, bb1);
                fma2(acc2[0][2], a0, bb2); fma2(acc2[1][2], a1, bb2);
                fma2(acc2[2][2], a2, bb2); fma2(acc2[3][2], a3, bb2);
                fma2(acc2[0][3], a0, bb3); fma2(acc2[1][3], a1, bb3);
                fma2(acc2[2][3], a2, bb3); fma2(acc2[3][3], a3, bb3);
            }
            if (t+1 < NT){
                Asb[nb*1024 + (ac+0)*64+ar] = pa0.x; Asb[nb*1024 + (ac+1)*64+ar] = pa0.y;
                Asb[nb*1024 + (ac+2)*64+ar] = pa0.z; Asb[nb*1024 + (ac+3)*64+ar] = pa0.w;
                Asb[nb*1024 + (ac+4)*64+ar] = pa1.x; Asb[nb*1024 + (ac+5)*64+ar] = pa1.y;
                Asb[nb*1024 + (ac+6)*64+ar] = pa1.z; Asb[nb*1024 + (ac+7)*64+ar] = pa1.w;
                CP_WAIT0();
                __syncthreads();
                buf = nb;
            }
        }

        float bj0 = bias[col0+n0+0], bj1 = bias[col0+n0+1];
        float bj2 = bias[col0+n0+2], bj3 = bias[col0+n0+3];
#pragma unroll
        for (int i2=0;i2<4;i2++){
            int rowA = row0 + m0 + 2*i2;
            int rowB = rowA + 1;
            float2 p0 = unpack2(acc2[i2][0]);
            float2 p1 = unpack2(acc2[i2][1]);
            float2 p2 = unpack2(acc2[i2][2]);
            float2 p3 = unpack2(acc2[i2][3]);
            float vA[4] = {p0.x+bj0, p1.x+bj1, p2.x+bj2, p3.x+bj3};
            float vB[4] = {p0.y+bj0, p1.y+bj1, p2.y+bj2, p3.y+bj3};
            int bA = rowA >> 11, nA = rowA & 2047;
            int bB = rowB >> 11, nB = rowB & 2047;
#pragma unroll
            for (int j=0;j<4;j++){
                int col = col0 + n0 + j;
                int h = col / 192;
                int remc = col - h*192;
                int d = remc / 3;
                int s = remc - d*3;
                long long offA = ((long long)(bA*H_ + h)*N_ + nA)*D_ + d;
                long long offB = ((long long)(bB*H_ + h)*N_ + nB)*D_ + d;
                if (s == 0){ g_q[offA] = vA[j]; g_q[offB] = vB[j]; }
                else if (s == 1){ g_k[offA] = vA[j]; g_k[offB] = vB[j]; }
                else { g_v[offA] = vA[j]; g_v[offB] = vB[j]; }
            }
        }
    }
    else {
        // ================= top-k role (128 threads, 16 keys/thread; bit-identical selection) =================
        int* hist    = (int*)sbuf;          // 256 bins
        int* scratch = ((int*)sbuf) + 256;  // 4 ints

        const int row = grp*16 + (rem - 3);   // 0..16383
        const int w = row & (NW_-1);
        unsigned base = (unsigned)row * 2048u;

        unsigned kk[16];
#pragma unroll
        for (int q=0; q<16; q++){
            int n = tid*16 + q;
            unsigned i = base + (unsigned)n;
            unsigned o0, o1;
            threefry_0_1(0u, i, o0, o1);
            unsigned bits = o0 ^ o1;
            float u = __uint_as_float((bits >> 9) | 0x3F800000u) - 1.0f;
            float noise = 3.0f * expf(-0.5f * log1pf(-u));
            int jblk = n >> 2;
            int dd = w - jblk; if (dd < 0) dd = -dd;
            float score = (float)dd - noise;
            unsigned fb = __float_as_uint(score);
            kk[q] = (fb & 0x80000000u) ? ~fb : (fb | 0x80000000u);
        }

        unsigned prefix = 0, mask = 0;
        int target = KEEP_;
#pragma unroll 1
        for (int pass = 0; pass < 4; pass++){
            int shift = 24 - 8*pass;
            hist[2*tid] = 0; hist[2*tid+1] = 0;
            __syncthreads();
#pragma unroll
            for (int q=0; q<16; q++){
                if ((kk[q] & mask) == prefix) atomicAdd(&hist[(kk[q] >> shift) & 255u], 1);
            }
            __syncthreads();
            int h0 = hist[2*tid], h1 = hist[2*tid+1];
            int excl = scan128_excl(h0 + h1, tid, scratch);
            if (excl < target && target <= excl + h0){
                s_prefix = prefix | ((unsigned)(2*tid) << shift);
                s_target = target - excl;
            }
            int e1 = excl + h0;
            if (e1 < target && target <= e1 + h1){
                s_prefix = prefix | ((unsigned)(2*tid+1) << shift);
                s_target = target - e1;
            }
            __syncthreads();
            prefix = s_prefix; target = s_target;
            mask |= (0xFFu << shift);
        }
        unsigned T = prefix;
        int r = target;

        int eq_cnt = 0;
#pragma unroll
        for (int q=0;q<16;q++) eq_cnt += (kk[q] == T);
        int eq_off = scan128_excl(eq_cnt, tid, scratch);

        unsigned chflag = 0; int ch_cnt = 0; int er = eq_off;
#pragma unroll
        for (int q=0;q<16;q++){
            unsigned k = kk[q];
            bool ch = false;
            if (k < T) ch = true;
            else if (k == T){ ch = (er < r); er++; }
            if (ch){ chflag |= (1u<<q); ch_cnt++; }
        }
        int pos = scan128_excl(ch_cnt, tid, scratch);
#pragma unroll
        for (int q=0;q<16;q++){
            if (chflag & (1u<<q)){
                g_idx[row*KEEP_ + pos] = tid*16 + q;
                pos++;
            }
        }
    }
}

// ---------------- Position-bias MLP: table (4095, 8) ----------------
__global__ void pb_kernel(const float* __restrict__ w0, const float* __restrict__ b0,
                          const float* __restrict__ w1, const float* __restrict__ b1,
                          const float* __restrict__ w2, const float* __restrict__ b2)
{
    __shared__ float h0[16*512];
    int tid = threadIdx.x;
    int r0 = blockIdx.x * 16;

    for (int i = tid; i < 16*512; i += 256){
        int r = i >> 9, j = i & 511;
        int rr = r0 + r;
        float v = 0.f;
        if (rr < 2*N_-1){
            float pos = (float)(rr - (N_-1));
            float t = pos * w0[j] + b0[j];
            v = t / (1.f + expf(-t));
        }
        h0[r*512 + j] = v;
    }
    __syncthreads();

    float acc[2][16];
#pragma unroll
    for (int c=0;c<2;c++)
#pragma unroll
        for (int r=0;r<16;r++) acc[c][r]=0.f;

    for (int k=0;k<512;k++){
        float wA = w1[k*512 + tid];
        float wB = w1[k*512 + tid + 256];
#pragma unroll
        for (int r=0;r<16;r++){
            float hv = h0[r*512 + k];
            acc[0][r] += hv*wA;
            acc[1][r] += hv*wB;
        }
    }
    __syncthreads();

#pragma unroll
    for (int c=0;c<2;c++){
        int j = tid + c*256;
        float bb = b1[j];
#pragma unroll
        for (int r=0;r<16;r++){
            float t = acc[c][r] + bb;
            h0[r*512 + j] = t / (1.f + expf(-t));
        }
    }
    __syncthreads();

    int warp = tid >> 5, lane = tid & 31;
    for (int task = warp; task < 128; task += 8){
        int r = task >> 3, o = task & 7;
        float s = 0.f;
        for (int k = lane; k < 512; k += 32) s += h0[r*512 + k] * w2[k*8 + o];
#pragma unroll
        for (int off=16; off; off>>=1) s += __shfl_xor_sync(0xffffffffu, s, off);
        if (lane == 0){
            int rr = r0 + r;
            if (rr < 2*N_-1) g_tab[rr*8 + o] = s + b2[o];
        }
    }
}

// ---------------- attention per (b,h,blk): reads g_idx (R4/R11-verified body) ----------------
__global__ __launch_bounds__(256) void attn_kernel()
{
    __shared__ float qs[4*64];
    __shared__ float ks[64*68];
    __shared__ float vs[64*68];
    __shared__ float sv[4*64];
    __shared__ float pm[4], psum[4];
    __shared__ int sidx[64];

    int row = blockIdx.x, tid = threadIdx.x;
    int w = row & (NW_-1);
    int bh = row >> 9;
    int h = bh & 7, b = bh >> 3;

    if (tid < 64) sidx[tid] = g_idx[row*KEEP_ + tid];
    __syncthreads();

    const float4* kb4 = (const float4*)(g_k + (long long)bh * N_ * D_);
    const float4* vb4 = (const float4*)(g_v + (long long)bh * N_ * D_);
    const float* qbase = g_q + ((long long)bh * N_ + w*W_) * D_;

    qs[tid] = qbase[tid];
    for (int i = tid; i < 64*16; i += 256){
        int z = i >> 4, d4 = i & 15;
        int key = sidx[z];
        *(float4*)&ks[z*68 + d4*4] = kb4[key*16 + d4];
        *(float4*)&vs[z*68 + d4*4] = vb4[key*16 + d4];
    }
    __syncthreads();

    int wi = tid >> 6, z = tid & 63;
    const float4* qs4 = (const float4*)qs;
    const float4* ks4 = (const float4*)ks;
    float acc = 0.f;
#pragma unroll
    for (int d4=0; d4<16; d4++){
        float4 qv = qs4[wi*16 + d4];
        float4 kv = ks4[z*17 + d4];
        acc += qv.x*kv.x + qv.y*kv.y + qv.z*kv.z + qv.w*kv.w;
    }
    int rel = (w*W_ + wi) - sidx[z] + (N_-1);
    float val = acc * 0.125f + g_tab[rel*8 + h];
    sv[tid] = val;
    __syncthreads();

    if (tid < 128){
        int wr = tid >> 5, lane = tid & 31;
        float v1 = sv[wr*64 + lane], v2 = sv[wr*64 + lane + 32];
        float m = fmaxf(v1, v2);
#pragma unroll
        for (int off=16; off; off>>=1) m = fmaxf(m, __shfl_xor_sync(0xffffffffu, m, off));
        float s = expf(v1 - m) + expf(v2 - m);
#pragma unroll
        for (int off=16; off; off>>=1) s += __shfl_xor_sync(0xffffffffu, s, off);
        if (lane == 0){ pm[wr] = m; psum[wr] = s; }
    }
    __syncthreads();

    float p = expf(val - pm[wi]) / psum[wi];
    sv[tid] = p;
    __syncthreads();

    int d = z;
    const float4* sv4 = (const float4*)sv;
    float o = 0.f;
#pragma unroll
    for (int z4=0; z4<16; z4++){
        float4 p4 = sv4[wi*16 + z4];
        o += p4.x*vs[(z4*4+0)*68 + d] + p4.y*vs[(z4*4+1)*68 + d]
           + p4.z*vs[(z4*4+2)*68 + d] + p4.w*vs[(z4*4+3)*68 + d];
    }
    g_attn[(((long long)b*N_ + w*W_ + wi)*H_ + h)*D_ + d] = o;
}

// ---------------- GEMM 2: output projection (R15 out64_kernel, passed) ----------------
__global__ __launch_bounds__(128) void out64_kernel(const float* __restrict__ Bm,
                                                    const float* __restrict__ bias,
                                                    float* __restrict__ C)
{
    __shared__ float As[2][BK][TBN];
    __shared__ float Bs[2][BK][TBN];
    const int tid = threadIdx.x;
    const int row0 = blockIdx.y*64, col0 = blockIdx.x*64;

    const int ar = tid>>1;
    const int ac = (tid&1)*8;
    const int br = tid>>3;
    const int bc = (tid&7)*8;

    const int warp = tid>>5, lane = tid&31;
    const int wm = warp&1, wn = warp>>1;
    const int tr = lane>>3, tc = lane&7;
    const int m0 = wm*32 + tr*8;
    const int n0 = wn*32 + tc*4;

    const uint32_t bs_base = (uint32_t)__cvta_generic_to_shared(&Bs[0][0][0]);
    const uint32_t boff0 = (uint32_t)(br*TBN + bc)*4u;
    const uint32_t boff1 = boff0 + 16u;

    u64 acc2[4][4];
#pragma unroll
    for (int i2=0;i2<4;i2++)
#pragma unroll
        for (int j=0;j<4;j++) acc2[i2][j]=0ull;

    cp_async16(bs_base + boff0, &Bm[br*NF_ + col0+bc]);
    cp_async16(bs_base + boff1, &Bm[br*NF_ + col0+bc+4]);
    CP_COMMIT();
    float4 pa0 = *(const float4*)&g_attn[(long long)(row0+ar)*NF_ + ac];
    float4 pa1 = *(const float4*)&g_attn[(long long)(row0+ar)*NF_ + ac+4];
    As[0][ac+0][ar] = pa0.x; As[0][ac+1][ar] = pa0.y; As[0][ac+2][ar] = pa0.z; As[0][ac+3][ar] = pa0.w;
    As[0][ac+4][ar] = pa1.x; As[0][ac+5][ar] = pa1.y; As[0][ac+6][ar] = pa1.z; As[0][ac+7][ar] = pa1.w;
    CP_WAIT0();
    __syncthreads();

    int buf = 0;
    const int NT = NF_/BK;
    for (int t=0; t<NT; t++){
        const int k0n = (t+1)*BK;
        const int nb = buf^1;
        if (t+1 < NT){
            uint32_t nbb = bs_base + (uint32_t)nb*(BK*TBN*4u);
            cp_async16(nbb + boff0, &Bm[(k0n+br)*NF_ + col0+bc]);
            cp_async16(nbb + boff1, &Bm[(k0n+br)*NF_ + col0+bc+4]);
            CP_COMMIT();
            pa0 = *(const float4*)&g_attn[(long long)(row0+ar)*NF_ + k0n+ac];
            pa1 = *(const float4*)&g_attn[(long long)(row0+ar)*NF_ + k0n+ac+4];
        }
#pragma unroll
        for (int kk=0; kk<BK; kk++){
            const u64* av = (const u64*)&As[buf][kk][m0];
            u64 a0 = av[0], a1 = av[1], a2 = av[2], a3 = av[3];
            float4 b = *(const float4*)&Bs[buf][kk][n0];
            u64 bb0 = pack2(b.x), bb1 = pack2(b.y), bb2 = pack2(b.z), bb3 = pack2(b.w);
            fma2(acc2[0][0], a0, bb0); fma2(acc2[1][0], a1, bb0);
            fma2(acc2[2][0], a2, bb0); fma2(acc2[3][0], a3, bb0);
            fma2(acc2[0][1], a0, bb1); fma2(acc2[1][1], a1, bb1);
            fma2(acc2[2][1], a2, bb1); fma2(acc2[3][1], a3, bb1);
            fma2(acc2[0][2], a0, bb2); fma2(acc2[1][2], a1, bb2);
            fma2(acc2[2][2], a2, bb2); fma2(acc2[3][2], a3, bb2);
            fma2(acc2[0][3], a0, bb3); fma2(acc2[1][3], a1, bb3);
            fma2(acc2[2][3], a2, bb3); fma2(acc2[3][3], a3, bb3);
        }
        if (t+1 < NT){
            As[nb][ac+0][ar] = pa0.x; As[nb][ac+1][ar] = pa0.y; As[nb][ac+2][ar] = pa0.z; As[nb][ac+3][ar] = pa0.w;
            As[nb][ac+4][ar] = pa1.x; As[nb][ac+5][ar] = pa1.y; As[nb][ac+6][ar] = pa1.z; As[nb][ac+7][ar] = pa1.w;
            CP_WAIT0();
            __syncthreads();
            buf = nb;
        }
    }

    float bj0 = bias[col0+n0+0], bj1 = bias[col0+n0+1];
    float bj2 = bias[col0+n0+2], bj3 = bias[col0+n0+3];
#pragma unroll
    for (int i2=0;i2<4;i2++){
        int rowA = row0 + m0 + 2*i2;
        int rowB = rowA + 1;
        float2 p0 = unpack2(acc2[i2][0]);
        float2 p1 = unpack2(acc2[i2][1]);
        float2 p2 = unpack2(acc2[i2][2]);
        float2 p3 = unpack2(acc2[i2][3]);
        *(float4*)&C[(long long)rowA*NF_ + col0+n0] = make_float4(p0.x+bj0, p1.x+bj1, p2.x+bj2, p3.x+bj3);
        *(float4*)&C[(long long)rowB*NF_ + col0+n0] = make_float4(p0.y+bj0, p1.y+bj1, p2.y+bj2, p3.y+bj3);
    }
}

// ---------------- launch ----------------
extern "C" void kernel_launch(void* const* d_in, const int* in_sizes, int n_in,
                              void* d_out, int out_size)
{
    const float *x, *Wqkv, *bqkv, *Wout, *bout;
    const float *pb_w0, *pb_b0, *pb_w1, *pb_b1, *pb_w2, *pb_b2;

    if (in_sizes[0] == 4194304) {
        x     = (const float*)d_in[0];
        Wqkv  = (const float*)d_in[1];
        bqkv  = (const float*)d_in[2];
        Wout  = (const float*)d_in[3];
        bout  = (const float*)d_in[4];
        pb_w0 = (const float*)d_in[5];
        pb_b0 = (const float*)d_in[6];
        pb_w1 = (const float*)d_in[7];
        pb_b1 = (const float*)d_in[8];
        pb_w2 = (const float*)d_in[9];
        pb_b2 = (const float*)d_in[10];
    } else {
        Wout  = (const float*)d_in[0];
        Wqkv  = (const float*)d_in[1];
        bout  = (const float*)d_in[2];
        bqkv  = (const float*)d_in[3];
        pb_b0 = (const float*)d_in[4];
        pb_b1 = (const float*)d_in[5];
        pb_b2 = (const float*)d_in[6];
        pb_w0 = (const float*)d_in[7];
        pb_w1 = (const float*)d_in[8];
        pb_w2 = (const float*)d_in[9];
        x     = (const float*)d_in[10];
    }
    float* out = (float*)d_out;

    pb_kernel<<<256, 256>>>(pb_w0, pb_b0, pb_w1, pb_b1, pb_w2, pb_b2);
    hetero128_kernel<<<HET_BLOCKS, 128>>>(x, Wqkv, bqkv);
    attn_kernel<<<NROWS, 256>>>();
    out64_kernel<<<dim3(NF_/64, (B_*N_)/64), 128>>>(Wout, bout, out);
}

// round 17
// speedup vs baseline: 1.1836x; 1.1836x over previous
#include <cuda_runtime.h>
#include <cuda_bf16.h>
#include <stdint.h>

// Problem constants
#define B_   4
#define N_   2048
#define NF_  512
#define H_   8
#define D_   64
#define W_   4
#define NW_  512          // N_/W_
#define KEEP_ 64
#define QKVN 1536         // 3*H*D
#define NROWS (B_*H_*NW_) // 16384
#define BHND (B_*H_*N_*D_)

// MMA GEMM tiling: block 128(M) x 64(N) x 32(K); 8 warps (4x2), warp tile 32x32
#define AST 40   // A smem stride (bf16) -> conflict-free frag loads
#define BST 42   // B smem stride (bf16)

// ---------------- device scratch (no allocations allowed) ----------------
__device__ float g_q[BHND];
__device__ float g_k[BHND];
__device__ float g_v[BHND];
__device__ float g_tab[(2*N_-1)*H_];      // 4095 x 8
__device__ float g_attn[B_*N_*H_*D_];     // (B, N, H*D)

// ---------------- threefry2x32 (JAX-compatible, key=(0,1)) ----------------
__device__ __forceinline__ uint32_t rotl32(uint32_t x, int r){ return (x<<r) | (x>>(32-r)); }

__device__ __forceinline__ void threefry_0_1(uint32_t c0, uint32_t c1, uint32_t& o0, uint32_t& o1){
    const uint32_t ks0 = 0u, ks1 = 1u, ks2 = 0x1BD11BDBu;
    uint32_t x0 = c0 + ks0;
    uint32_t x1 = c1 + ks1;
#define QR(r) { x0 += x1; x1 = rotl32(x1, r); x1 ^= x0; }
    QR(13) QR(15) QR(26) QR(6)   x0 += ks1; x1 += ks2 + 1u;
    QR(17) QR(29) QR(16) QR(24)  x0 += ks2; x1 += ks0 + 2u;
    QR(13) QR(15) QR(26) QR(6)   x0 += ks0; x1 += ks1 + 3u;
    QR(17) QR(29) QR(16) QR(24)  x0 += ks1; x1 += ks2 + 4u;
    QR(13) QR(15) QR(26) QR(6)   x0 += ks2; x1 += ks0 + 5u;
#undef QR
    o0 = x0; o1 = x1;
}

// ---------------- bf16 helpers ----------------
__device__ __forceinline__ uint32_t pack_bf16(float a, float b){
    __nv_bfloat16 ha = __float2bfloat16_rn(a);
    __nv_bfloat16 hb = __float2bfloat16_rn(b);
    return (uint32_t)__bfloat16_as_ushort(ha) | ((uint32_t)__bfloat16_as_ushort(hb) << 16);
}

// mma on NAMED registers only (float4& / uint4)
#define MMA4(c, a, b0, b1) \
    asm volatile( \
        "mma.sync.aligned.m16n8k16.row.col.f32.bf16.bf16.f32 " \
        "{%0,%1,%2,%3}, {%4,%5,%6,%7}, {%8,%9}, {%0,%1,%2,%3};\n" \
        : "+f"((c).x), "+f"((c).y), "+f"((c).z), "+f"((c).w) \
        : "r"((a).x), "r"((a).y), "r"((a).z), "r"((a).w), "r"(b0), "r"(b1))

// shared mainloop body (A tile load, B tile load, 3-term mma) expanded in both kernels.
#define GEMM_MMA_BODY(APTR, LDB)                                                          \
    const int tid = threadIdx.x;                                                          \
    const int row0 = blockIdx.y*128, col0 = blockIdx.x*64;                                \
    const int wid = tid>>5, lane = tid&31;                                                \
    const int wm = wid&3, wn = wid>>2;                                                    \
    const int g = lane>>2, tig = lane&3;                                                  \
    float4 acc00 = make_float4(0.f,0.f,0.f,0.f), acc01 = acc00, acc02 = acc00, acc03 = acc00; \
    float4 acc10 = acc00, acc11 = acc00, acc12 = acc00, acc13 = acc00;                    \
    const int ar = tid>>1;                                                                \
    const int acb = (tid&1)*16;                                                           \
    const int bk = tid>>3;                                                                \
    const int bcg = tid&7;                                                                \
    for (int k0 = 0; k0 < NF_; k0 += 32){                                                 \
        __syncthreads();                                                                  \
        _Pragma("unroll")                                                                 \
        for (int j=0;j<4;j++){                                                            \
            float4 v = *(const float4*)&APTR[(long long)(row0+ar)*NF_ + k0 + acb + 4*j];  \
            float hx = __bfloat162float(__float2bfloat16_rn(v.x));                        \
            float hy = __bfloat162float(__float2bfloat16_rn(v.y));                        \
            float hz = __bfloat162float(__float2bfloat16_rn(v.z));                        \
            float hw = __bfloat162float(__float2bfloat16_rn(v.w));                        \
            int base = ar*AST + acb + 4*j;                                                \
            *(uint32_t*)&Ahi[base]   = pack_bf16(v.x, v.y);                               \
            *(uint32_t*)&Ahi[base+2] = pack_bf16(v.z, v.w);                               \
            *(uint32_t*)&Alo[base]   = pack_bf16(v.x-hx, v.y-hy);                         \
            *(uint32_t*)&Alo[base+2] = pack_bf16(v.z-hz, v.w-hw);                         \
        }                                                                                 \
        _Pragma("unroll")                                                                 \
        for (int j=0;j<2;j++){                                                            \
            int nb = (bcg + 8*j)*4;                                                       \
            float4 v = *(const float4*)&Bm[(long long)(k0+bk)*(LDB) + col0 + nb];         \
            float hx = __bfloat162float(__float2bfloat16_rn(v.x));                        \
            float hy = __bfloat162float(__float2bfloat16_rn(v.y));                        \
            float hz = __bfloat162float(__float2bfloat16_rn(v.z));                        \
            float hw = __bfloat162float(__float2bfloat16_rn(v.w));                        \
            Bhi[(nb+0)*BST + bk] = __float2bfloat16_rn(v.x);                              \
            Bhi[(nb+1)*BST + bk] = __float2bfloat16_rn(v.y);                              \
            Bhi[(nb+2)*BST + bk] = __float2bfloat16_rn(v.z);                              \
            Bhi[(nb+3)*BST + bk] = __float2bfloat16_rn(v.w);                              \
            Blo[(nb+0)*BST + bk] = __float2bfloat16_rn(v.x-hx);                           \
            Blo[(nb+1)*BST + bk] = __float2bfloat16_rn(v.y-hy);                           \
            Blo[(nb+2)*BST + bk] = __float2bfloat16_rn(v.z-hz);                           \
            Blo[(nb+3)*BST + bk] = __float2bfloat16_rn(v.w-hw);                           \
        }                                                                                 \
        __syncthreads();                                                                  \
        _Pragma("unroll")                                                                 \
        for (int ks=0; ks<32; ks+=16){                                                    \
            const int base0 = (wm*32 + g)*AST + ks + tig*2;                               \
            const int base1 = base0 + 16*AST;                                             \
            uint4 ah0, al0, ah1, al1;                                                     \
            ah0.x = *(const uint32_t*)&Ahi[base0];                                        \
            ah0.y = *(const uint32_t*)&Ahi[base0 + 8*AST];                                \
            ah0.z = *(const uint32_t*)&Ahi[base0 + 8];                                    \
            ah0.w = *(const uint32_t*)&Ahi[base0 + 8*AST + 8];                            \
            al0.x = *(const uint32_t*)&Alo[base0];                                        \
            al0.y = *(const uint32_t*)&Alo[base0 + 8*AST];                                \
            al0.z = *(const uint32_t*)&Alo[base0 + 8];                                    \
            al0.w = *(const uint32_t*)&Alo[base0 + 8*AST + 8];                            \
            ah1.x = *(const uint32_t*)&Ahi[base1];                                        \
            ah1.y = *(const uint32_t*)&Ahi[base1 + 8*AST];                                \
            ah1.z = *(const uint32_t*)&Ahi[base1 + 8];                                    \
            ah1.w = *(const uint32_t*)&Ahi[base1 + 8*AST + 8];                            \
            al1.x = *(const uint32_t*)&Alo[base1];                                        \
            al1.y = *(const uint32_t*)&Alo[base1 + 8*AST];                                \
            al1.z = *(const uint32_t*)&Alo[base1 + 8];                                    \
            al1.w = *(const uint32_t*)&Alo[base1 + 8*AST + 8];                            \
            MMA_STEP(0, acc00, acc10)                                                     \
            MMA_STEP(1, acc01, acc11)                                                     \
            MMA_STEP(2, acc02, acc12)                                                     \
            MMA_STEP(3, acc03, acc13)                                                     \
        }                                                                                 \
    }

#define MMA_STEP(J, ACC0, ACC1) {                                   \
    int bbase = (wn*32 + (J)*8 + g)*BST + ks + tig*2;               \
    uint32_t bh0 = *(const uint32_t*)&Bhi[bbase];                   \
    uint32_t bh1 = *(const uint32_t*)&Bhi[bbase + 8];               \
    uint32_t bl0 = *(const uint32_t*)&Blo[bbase];                   \
    uint32_t bl1 = *(const uint32_t*)&Blo[bbase + 8];               \
    MMA4(ACC0, ah0, bh0, bh1);                                      \
    MMA4(ACC0, ah0, bl0, bl1);                                      \
    MMA4(ACC0, al0, bh0, bh1);                                      \
    MMA4(ACC1, ah1, bh0, bh1);                                      \
    MMA4(ACC1, ah1, bl0, bl1);                                      \
    MMA4(ACC1, al1, bh0, bh1); }

// ---------------- GEMM 1: QKV projection (tensor-core; non-template) ----------------
__global__ __launch_bounds__(256) void qkv_mma_kernel(const float* __restrict__ A,
                                                      const float* __restrict__ Bm,
                                                      const float* __restrict__ bias)
{
    __shared__ __nv_bfloat16 Ahi[128*AST];
    __shared__ __nv_bfloat16 Alo[128*AST];
    __shared__ __nv_bfloat16 Bhi[64*BST];
    __shared__ __nv_bfloat16 Blo[64*BST];

    GEMM_MMA_BODY(A, QKVN)

    // epilogue: scatter into q/k/v (B,H,N,D)
#define EPIQ(J, ACCV, T) {                                                      \
    int rb = row0 + wm*32 + (T)*16 + g;                                         \
    int cb = col0 + wn*32 + (J)*8 + tig*2;                                      \
    float e0 = (ACCV).x + bias[cb];                                             \
    float e1 = (ACCV).y + bias[cb+1];                                           \
    float e2 = (ACCV).z + bias[cb];                                             \
    float e3 = (ACCV).w + bias[cb+1];                                           \
    for (int q2=0;q2<4;q2++){                                                   \
        int row = rb + ((q2>=2)?8:0);                                           \
        int col = cb + (q2&1);                                                  \
        float val = (q2==0)?e0:((q2==1)?e1:((q2==2)?e2:e3));                    \
        int b = row >> 11, n = row & 2047;                                      \
        int h = col / 192;                                                      \
        int rem = col - h*192;                                                  \
        int d = rem / 3;                                                        \
        int s = rem - d*3;                                                      \
        long long off = ((long long)(b*H_ + h)*N_ + n)*D_ + d;                  \
        if (s == 0) g_q[off] = val;                                             \
        else if (s == 1) g_k[off] = val;                                        \
        else g_v[off] = val;                                                    \
    } }

    EPIQ(0, acc00, 0) EPIQ(1, acc01, 0) EPIQ(2, acc02, 0) EPIQ(3, acc03, 0)
    EPIQ(0, acc10, 1) EPIQ(1, acc11, 1) EPIQ(2, acc12, 1) EPIQ(3, acc13, 1)
#undef EPIQ
}

// ---------------- GEMM 2: output projection (tensor-core; non-template; reads g_attn) ----------------
__global__ __launch_bounds__(256) void out_mma_kernel(const float* __restrict__ Bm,
                                                      const float* __restrict__ bias,
                                                      float* __restrict__ C)
{
    __shared__ __nv_bfloat16 Ahi[128*AST];
    __shared__ __nv_bfloat16 Alo[128*AST];
    __shared__ __nv_bfloat16 Bhi[64*BST];
    __shared__ __nv_bfloat16 Blo[64*BST];

    GEMM_MMA_BODY(g_attn, NF_)

#define EPIO(J, ACCV, T) {                                                      \
    int rb = row0 + wm*32 + (T)*16 + g;                                         \
    int cb = col0 + wn*32 + (J)*8 + tig*2;                                      \
    float b0v = bias[cb], b1v = bias[cb+1];                                     \
    C[(long long)rb*NF_ + cb]       = (ACCV).x + b0v;                           \
    C[(long long)rb*NF_ + cb+1]     = (ACCV).y + b1v;                           \
    C[(long long)(rb+8)*NF_ + cb]   = (ACCV).z + b0v;                           \
    C[(long long)(rb+8)*NF_ + cb+1] = (ACCV).w + b1v; }

    EPIO(0, acc00, 0) EPIO(1, acc01, 0) EPIO(2, acc02, 0) EPIO(3, acc03, 0)
    EPIO(0, acc10, 1) EPIO(1, acc11, 1) EPIO(2, acc12, 1) EPIO(3, acc13, 1)
#undef EPIO
}

// ---------------- Position-bias MLP: table (4095, 8) ----------------
__global__ void pb_kernel(const float* __restrict__ w0, const float* __restrict__ b0,
                          const float* __restrict__ w1, const float* __restrict__ b1,
                          const float* __restrict__ w2, const float* __restrict__ b2)
{
    __shared__ float h0[16*512];
    int tid = threadIdx.x;
    int r0 = blockIdx.x * 16;

    for (int i = tid; i < 16*512; i += 256){
        int r = i >> 9, j = i & 511;
        int rr = r0 + r;
        float v = 0.f;
        if (rr < 2*N_-1){
            float pos = (float)(rr - (N_-1));
            float t = pos * w0[j] + b0[j];
            v = t / (1.f + expf(-t));
        }
        h0[r*512 + j] = v;
    }
    __syncthreads();

    float acc[2][16];
#pragma unroll
    for (int c=0;c<2;c++)
#pragma unroll
        for (int r=0;r<16;r++) acc[c][r]=0.f;

    for (int k=0;k<512;k++){
        float wA = w1[k*512 + tid];
        float wB = w1[k*512 + tid + 256];
#pragma unroll
        for (int r=0;r<16;r++){
            float hv = h0[r*512 + k];
            acc[0][r] += hv*wA;
            acc[1][r] += hv*wB;
        }
    }
    __syncthreads();

#pragma unroll
    for (int c=0;c<2;c++){
        int j = tid + c*256;
        float bb = b1[j];
#pragma unroll
        for (int r=0;r<16;r++){
            float t = acc[c][r] + bb;
            h0[r*512 + j] = t / (1.f + expf(-t));
        }
    }
    __syncthreads();

    int warp = tid >> 5, lane = tid & 31;
    for (int task = warp; task < 128; task += 8){
        int r = task >> 3, o = task & 7;
        float s = 0.f;
        for (int k = lane; k < 512; k += 32) s += h0[r*512 + k] * w2[k*8 + o];
#pragma unroll
        for (int off=16; off; off>>=1) s += __shfl_xor_sync(0xffffffffu, s, off);
        if (lane == 0){
            int rr = r0 + r;
            if (rr < 2*N_-1) g_tab[rr*8 + o] = s + b2[o];
        }
    }
}

// ---------------- fast block exclusive scan (256 threads) ----------------
__device__ __forceinline__ int block_scan_excl(int val, int tid, int* scratch){
    int lane = tid & 31, wid = tid >> 5;
    int x = val;
#pragma unroll
    for (int o=1; o<32; o<<=1){
        int t = __shfl_up_sync(0xffffffffu, x, o);
        if (lane >= o) x += t;
    }
    if (lane == 31) scratch[wid] = x;
    __syncthreads();
    if (wid == 0 && lane < 8){
        int y = scratch[lane];
#pragma unroll
        for (int o=1; o<8; o<<=1){
            int t = __shfl_up_sync(0xFFu, y, o);
            if (lane >= o) y += t;
        }
        scratch[lane] = y;
    }
    __syncthreads();
    int base = (wid == 0) ? 0 : scratch[wid-1];
    return base + x - val;
}

// ---------------- fused top-k + attention per (b,h,blk) (R11 champion body) ----------------
__global__ __launch_bounds__(256) void topk_attn_kernel()
{
    __shared__ float qs[4*64];
    __shared__ float ks[64*68];
    __shared__ float vs[64*68];
    __shared__ float sv[4*64];
    __shared__ float pm[4], psum[4];
    __shared__ int sidx[64];
    __shared__ unsigned s_prefix;
    __shared__ int s_target;

    int row = blockIdx.x, tid = threadIdx.x;
    int w = row & (NW_-1);
    int bh = row >> 9;
    int h = bh & 7, b = bh >> 3;

    int* hist    = (int*)ks;
    int* scratch = ((int*)ks) + 256;

    const float* qbase = g_q + ((long long)bh * N_ + w*W_) * D_;
    float qreg = qbase[tid];

    unsigned kk[8];
    unsigned base = (unsigned)row * 2048u;
#pragma unroll
    for (int q=0; q<8; q++){
        int n = tid*8 + q;
        unsigned i = base + (unsigned)n;
        unsigned o0, o1;
        threefry_0_1(0u, i, o0, o1);
        unsigned bits = o0 ^ o1;
        float u = __uint_as_float((bits >> 9) | 0x3F800000u) - 1.0f;
        float noise = 3.0f * expf(-0.5f * log1pf(-u));
        int jblk = n >> 2;
        int dd = w - jblk; if (dd < 0) dd = -dd;
        float score = (float)dd - noise;
        unsigned fb = __float_as_uint(score);
        kk[q] = (fb & 0x80000000u) ? ~fb : (fb | 0x80000000u);
    }

    unsigned prefix = 0, mask = 0;
    int target = KEEP_;
#pragma unroll 1
    for (int pass = 0; pass < 4; pass++){
        int shift = 24 - 8*pass;
        hist[tid] = 0;
        __syncthreads();
#pragma unroll
        for (int q=0; q<8; q++){
            if ((kk[q] & mask) == prefix) atomicAdd(&hist[(kk[q] >> shift) & 255u], 1);
        }
        __syncthreads();
        int hv = hist[tid];
        __syncthreads();
        int excl = block_scan_excl(hv, tid, scratch);
        int incl = excl + hv;
        if (excl < target && target <= incl){
            s_prefix = prefix | ((unsigned)tid << shift);
            s_target = target - excl;
        }
        __syncthreads();
        prefix = s_prefix; target = s_target;
        mask |= (0xFFu << shift);
    }
    unsigned T = prefix;
    int r = target;

    int eq_cnt = 0;
#pragma unroll
    for (int q=0;q<8;q++) eq_cnt += (kk[q] == T);
    int eq_off = block_scan_excl(eq_cnt, tid, scratch);

    unsigned chflag = 0; int ch_cnt = 0; int er = eq_off;
#pragma unroll
    for (int q=0;q<8;q++){
        unsigned k = kk[q];
        bool ch = false;
        if (k < T) ch = true;
        else if (k == T){ ch = (er < r); er++; }
        if (ch){ chflag |= (1u<<q); ch_cnt++; }
    }
    int pos = block_scan_excl(ch_cnt, tid, scratch);
#pragma unroll
    for (int q=0;q<8;q++){
        if (chflag & (1u<<q)){
            sidx[pos] = tid*8 + q;
            pos++;
        }
    }
    __syncthreads();

    // ---- attention phase ----
    const float4* kb4 = (const float4*)(g_k + (long long)bh * N_ * D_);
    const float4* vb4 = (const float4*)(g_v + (long long)bh * N_ * D_);

    qs[tid] = qreg;
    for (int i = tid; i < 64*16; i += 256){
        int z = i >> 4, d4 = i & 15;
        int key = sidx[z];
        *(float4*)&ks[z*68 + d4*4] = kb4[key*16 + d4];
        *(float4*)&vs[z*68 + d4*4] = vb4[key*16 + d4];
    }
    __syncthreads();

    int wi = tid >> 6, z = tid & 63;
    const float4* qs4 = (const float4*)qs;
    const float4* ks4 = (const float4*)ks;
    float acc = 0.f;
#pragma unroll
    for (int d4=0; d4<16; d4++){
        float4 qv = qs4[wi*16 + d4];
        float4 kv = ks4[z*17 + d4];
        acc += qv.x*kv.x + qv.y*kv.y + qv.z*kv.z + qv.w*kv.w;
    }
    int rel = (w*W_ + wi) - sidx[z] + (N_-1);
    float val = acc * 0.125f + g_tab[rel*8 + h];
    sv[tid] = val;
    __syncthreads();

    if (tid < 128){
        int wr = tid >> 5, lane = tid & 31;
        float v1 = sv[wr*64 + lane], v2 = sv[wr*64 + lane + 32];
        float m = fmaxf(v1, v2);
#pragma unroll
        for (int off=16; off; off>>=1) m = fmaxf(m, __shfl_xor_sync(0xffffffffu, m, off));
        float s = expf(v1 - m) + expf(v2 - m);
#pragma unroll
        for (int off=16; off; off>>=1) s += __shfl_xor_sync(0xffffffffu, s, off);
        if (lane == 0){ pm[wr] = m; psum[wr] = s; }
    }
    __syncthreads();

    float p = expf(val - pm[wi]) / psum[wi];
    sv[tid] = p;
    __syncthreads();

    int d = z;
    const float4* sv4 = (const float4*)sv;
    float o = 0.f;
#pragma unroll
    for (int z4=0; z4<16; z4++){
        float4 p4 = sv4[wi*16 + z4];
        o += p4.x*vs[(z4*4+0)*68 + d] + p4.y*vs[(z4*4+1)*68 + d]
           + p4.z*vs[(z4*4+2)*68 + d] + p4.w*vs[(z4*4+3)*68 + d];
    }
    g_attn[(((long long)b*N_ + w*W_ + wi)*H_ + h)*D_ + d] = o;
}

// ---------------- launch ----------------
extern "C" void kernel_launch(void* const* d_in, const int* in_sizes, int n_in,
                              void* d_out, int out_size)
{
    const float *x, *Wqkv, *bqkv, *Wout, *bout;
    const float *pb_w0, *pb_b0, *pb_w1, *pb_b1, *pb_w2, *pb_b2;

    if (in_sizes[0] == 4194304) {
        x     = (const float*)d_in[0];
        Wqkv  = (const float*)d_in[1];
        bqkv  = (const float*)d_in[2];
        Wout  = (const float*)d_in[3];
        bout  = (const float*)d_in[4];
        pb_w0 = (const float*)d_in[5];
        pb_b0 = (const float*)d_in[6];
        pb_w1 = (const float*)d_in[7];
        pb_b1 = (const float*)d_in[8];
        pb_w2 = (const float*)d_in[9];
        pb_b2 = (const float*)d_in[10];
    } else {
        Wout  = (const float*)d_in[0];
        Wqkv  = (const float*)d_in[1];
        bout  = (const float*)d_in[2];
        bqkv  = (const float*)d_in[3];
        pb_b0 = (const float*)d_in[4];
        pb_b1 = (const float*)d_in[5];
        pb_b2 = (const float*)d_in[6];
        pb_w0 = (const float*)d_in[7];
        pb_w1 = (const float*)d_in[8];
        pb_w2 = (const float*)d_in[9];
        x     = (const float*)d_in[10];
    }
    float* out = (float*)d_out;

    qkv_mma_kernel<<<dim3(QKVN/64, (B_*N_)/128), 256>>>(x, Wqkv, bqkv);
    pb_kernel<<<256, 256>>>(pb_w0, pb_b0, pb_w1, pb_b1, pb_w2, pb_b2);
    topk_attn_kernel<<<NROWS, 256>>>();
    out_mma_kernel<<<dim3(NF_/64, (B_*N_)/128), 256>>>(Wout, bout, out);
}